// round 13
// baseline (speedup 1.0000x reference)
#include <cuda_runtime.h>
#include <cuda_bf16.h>
#include <cstdint>

constexpr int NTOK = 4096;
constexpr int BH = 64, SPLITS = 8, NSEG = 512;
constexpr int CPS_A = NSEG / 64;     // 8 chunks of 64 tokens
constexpr int CPS_B = NSEG / 128;    // 4 chunks of 128 tokens
constexpr int NU = BH * SPLITS;      // 512 units per phase
constexpr int GRID = 296;

__device__ float    g_kv_part[(size_t)BH * SPLITS * 64 * 64];
__device__ unsigned g_arrive[BH];
__device__ unsigned g_ctrA, g_ctrB;

// ---- smem byte offsets ----
constexpr int LDA = 144;                              // 72-bf16 rows
constexpr int A_KH = 0, A_KL = 9216, A_VH = 18432, A_VL = 27648;
constexpr int S_WFH = 36864, S_WFL = 46080, S_BIAS = 55296;
constexpr int A_KVRED = 55552;                        // 2 x 16 KB
constexpr int LDQ = 272;
constexpr int B_QH = 0, B_QL = 17408;
constexpr int B_KVTH = 55552, B_KVTL = 64768;
constexpr int S_CLAIM = 88320;
constexpr int SMEM_TOTAL = 88448;

// ---------------- PTX helpers ----------------
__device__ __forceinline__ void ldsm4(uint32_t r[4], uint32_t a) {
    asm volatile("ldmatrix.sync.aligned.m8n8.x4.shared.b16 {%0,%1,%2,%3},[%4];"
                 : "=r"(r[0]), "=r"(r[1]), "=r"(r[2]), "=r"(r[3]) : "r"(a));
}
__device__ __forceinline__ void ldsm4t(uint32_t r[4], uint32_t a) {
    asm volatile("ldmatrix.sync.aligned.m8n8.x4.trans.shared.b16 {%0,%1,%2,%3},[%4];"
                 : "=r"(r[0]), "=r"(r[1]), "=r"(r[2]), "=r"(r[3]) : "r"(a));
}
// non-volatile: pure register op, compiler may schedule freely
__device__ __forceinline__ void mma_bf16(float c[4], const uint32_t a[4], const uint32_t b[2]) {
    asm("mma.sync.aligned.m16n8k16.row.col.f32.bf16.bf16.f32 "
        "{%0,%1,%2,%3},{%4,%5,%6,%7},{%8,%9},{%0,%1,%2,%3};"
        : "+f"(c[0]), "+f"(c[1]), "+f"(c[2]), "+f"(c[3])
        : "r"(a[0]), "r"(a[1]), "r"(a[2]), "r"(a[3]), "r"(b[0]), "r"(b[1]));
}
__device__ __forceinline__ uint32_t patA(uint32_t base, int ldB, int r0, int c0, int lane) {
    return base + (uint32_t)((r0 + (lane & 15)) * ldB + (c0 + ((lane >> 4) << 3)) * 2);
}
__device__ __forceinline__ uint32_t patB(uint32_t base, int ldB, int r0, int c0, int lane) {
    return base + (uint32_t)((r0 + (lane & 7) + ((lane >> 4) << 3)) * ldB
                             + (c0 + (((lane >> 3) & 1) << 3)) * 2);
}
__device__ __forceinline__ void split2(float x, __nv_bfloat16& hi, __nv_bfloat16& lo) {
    hi = __float2bfloat16(x);
    lo = __float2bfloat16(x - __bfloat162float(hi));
}
__device__ __forceinline__ void split_pack(float x0, float x1, uint32_t& hi, uint32_t& lo) {
    __nv_bfloat16 h0 = __float2bfloat16(x0), h1 = __float2bfloat16(x1);
    float r0 = x0 - __bfloat162float(h0), r1 = x1 - __bfloat162float(h1);
    __nv_bfloat162 hp = __halves2bfloat162(h0, h1);
    __nv_bfloat162 lp = __halves2bfloat162(__float2bfloat16(r0), __float2bfloat16(r1));
    hi = *(uint32_t*)&hp; lo = *(uint32_t*)&lp;
}
__device__ __forceinline__ void split_store4w(float4 x, __nv_bfloat16* hi, __nv_bfloat16* lo) {
    uint32_t h0, l0, h1, l1;
    split_pack(x.x, x.y, h0, l0);
    split_pack(x.z, x.w, h1, l1);
    *(uint2*)hi = make_uint2(h0, h1);
    *(uint2*)lo = make_uint2(l0, l1);
}
__device__ __forceinline__ void ld_tile64(const float* __restrict__ g, int tid, float4 r[4]) {
    #pragma unroll
    for (int i = 0; i < 4; i++) {
        int idx4 = tid + i * 256;
        r[i] = *(const float4*)(g + (size_t)(idx4 >> 4) * NTOK + (idx4 & 15) * 4);
    }
}
__device__ __forceinline__ void st_tile64(char* sm, int offH, int offL, const float4 r[4], int tid) {
    #pragma unroll
    for (int i = 0; i < 4; i++) {
        int idx4 = tid + i * 256;
        int row = idx4 >> 4, c = (idx4 & 15) * 4;
        split_store4w(r[i], (__nv_bfloat16*)(sm + offH) + row * 72 + c,
                            (__nv_bfloat16*)(sm + offL) + row * 72 + c);
    }
}
__device__ __forceinline__ void ld_tile128(const float* __restrict__ g, int tid, float4 r[8]) {
    #pragma unroll
    for (int i = 0; i < 8; i++) {
        int idx4 = tid + i * 256;
        r[i] = *(const float4*)(g + (size_t)(idx4 >> 5) * NTOK + (idx4 & 31) * 4);
    }
}
__device__ __forceinline__ void st_tile128(char* sm, int offH, int offL, const float4 r[8], int tid) {
    #pragma unroll
    for (int i = 0; i < 8; i++) {
        int idx4 = tid + i * 256;
        int row = idx4 >> 5, c = (idx4 & 31) * 4;
        split_store4w(r[i], (__nv_bfloat16*)(sm + offH) + row * 136 + c,
                            (__nv_bfloat16*)(sm + offL) + row * 136 + c);
    }
}

__global__ void resetk() {
    if (threadIdx.x == 0) { g_ctrA = 0; g_ctrB = 0; }
    if (threadIdx.x < BH) g_arrive[threadIdx.x] = 0;
}

__global__ void __launch_bounds__(256, 2) fused(const float* __restrict__ q,
                                                const float* __restrict__ k,
                                                const float* __restrict__ v,
                                                const float* __restrict__ Wf,
                                                const float* __restrict__ bf,
                                                float* __restrict__ out) {
    extern __shared__ __align__(16) char sm[];
    const uint32_t sm32 = (uint32_t)__cvta_generic_to_shared(sm);
    const int tid = threadIdx.x, lane = tid & 31, warp = tid >> 5;

    // Wf split (persists across all units)
    #pragma unroll
    for (int i = 0; i < 16; i++) {
        int idx = tid + i * 256;
        int r = idx >> 6, c = idx & 63;
        __nv_bfloat16 h, l;
        split2(Wf[idx], h, l);
        ((__nv_bfloat16*)(sm + S_WFH))[r * 72 + c] = h;
        ((__nv_bfloat16*)(sm + S_WFL))[r * 72 + c] = l;
    }
    if (tid < 64) ((float*)(sm + S_BIAS))[tid] = bf[tid];
    __syncthreads();

    const int rb = warp >> 1, nh = warp & 1;

    // ---- Wf fragments hoisted ONCE for the whole A phase (invariant across chunks/units) ----
    uint32_t whr[4][4], wlr[4][4];
    #pragma unroll
    for (int kk = 0; kk < 4; kk++) {
        ldsm4(whr[kk], patA(sm32 + S_WFH, LDA, rb * 16, kk * 16, lane));
        ldsm4(wlr[kk], patA(sm32 + S_WFL, LDA, rb * 16, kk * 16, lane));
    }

    // ======================= A-unit claim loop =======================
    for (;;) {
        __syncthreads();
        if (tid == 0) *(int*)(sm + S_CLAIM) = (int)atomicAdd(&g_ctrA, 1u);
        __syncthreads();
        const int u = *(volatile int*)(sm + S_CLAIM);
        if (u >= NU) break;
        const int bh = u >> 3, split = u & 7;

        const float bias_r0 = ((float*)(sm + S_BIAS))[rb * 16 + (lane >> 2)];
        const float bias_r1 = ((float*)(sm + S_BIAS))[rb * 16 + (lane >> 2) + 8];

        float kvacc[8][4];
        #pragma unroll
        for (int g = 0; g < 8; g++)
            #pragma unroll
            for (int j = 0; j < 4; j++) kvacc[g][j] = 0.0f;

        const float* kbase = k + (size_t)bh * 64 * NTOK + split * NSEG;
        const float* vbase = v + (size_t)bh * 64 * NTOK + split * NSEG;

        float4 kreg[4], vreg[4];
        ld_tile64(kbase, tid, kreg);
        ld_tile64(vbase, tid, vreg);

        for (int sc = 0; sc < CPS_A; sc++) {
            st_tile64(sm, A_KH, A_KL, kreg, tid);
            st_tile64(sm, A_VH, A_VL, vreg, tid);
            __syncthreads();
            if (sc + 1 < CPS_A) {
                ld_tile64(kbase + (sc + 1) * 64, tid, kreg);
                ld_tile64(vbase + (sc + 1) * 64, tid, vreg);
            }

            float c[2][2][4];
            #pragma unroll
            for (int t = 0; t < 2; t++)
                #pragma unroll
                for (int g = 0; g < 2; g++)
                    #pragma unroll
                    for (int j = 0; j < 4; j++) c[t][g][j] = 0.0f;

            #pragma unroll
            for (int kk = 0; kk < 4; kk++) {
                #pragma unroll
                for (int t = 0; t < 2; t++) {
                    const int n0 = nh * 32 + t * 16;
                    uint32_t bh4[4], bl4[4];
                    ldsm4t(bh4, patA(sm32 + A_KH, LDA, kk * 16, n0, lane));
                    ldsm4t(bl4, patA(sm32 + A_KL, LDA, kk * 16, n0, lane));
                    mma_bf16(c[t][0], whr[kk], bh4);     mma_bf16(c[t][1], whr[kk], bh4 + 2);
                    mma_bf16(c[t][0], whr[kk], bl4);     mma_bf16(c[t][1], whr[kk], bl4 + 2);
                    mma_bf16(c[t][0], wlr[kk], bh4);     mma_bf16(c[t][1], wlr[kk], bh4 + 2);
                }
            }

            uint32_t ah[2][4], al[2][4];
            #pragma unroll
            for (int t = 0; t < 2; t++) {
                float v00 = fmaxf(c[t][0][0] + bias_r0, 0.f), v01 = fmaxf(c[t][0][1] + bias_r0, 0.f);
                float v02 = fmaxf(c[t][0][2] + bias_r1, 0.f), v03 = fmaxf(c[t][0][3] + bias_r1, 0.f);
                float v10 = fmaxf(c[t][1][0] + bias_r0, 0.f), v11 = fmaxf(c[t][1][1] + bias_r0, 0.f);
                float v12 = fmaxf(c[t][1][2] + bias_r1, 0.f), v13 = fmaxf(c[t][1][3] + bias_r1, 0.f);
                split_pack(v00, v01, ah[t][0], al[t][0]);
                split_pack(v02, v03, ah[t][1], al[t][1]);
                split_pack(v10, v11, ah[t][2], al[t][2]);
                split_pack(v12, v13, ah[t][3], al[t][3]);
            }

            #pragma unroll
            for (int g4 = 0; g4 < 4; g4++) {
                #pragma unroll
                for (int t = 0; t < 2; t++) {
                    const int n0 = nh * 32 + t * 16;
                    uint32_t vh4[4], vl4[4];
                    ldsm4(vh4, patB(sm32 + A_VH, LDA, g4 * 16, n0, lane));
                    ldsm4(vl4, patB(sm32 + A_VL, LDA, g4 * 16, n0, lane));
                    mma_bf16(kvacc[2 * g4], ah[t], vh4);     mma_bf16(kvacc[2 * g4 + 1], ah[t], vh4 + 2);
                    mma_bf16(kvacc[2 * g4], ah[t], vl4);     mma_bf16(kvacc[2 * g4 + 1], ah[t], vl4 + 2);
                    mma_bf16(kvacc[2 * g4], al[t], vh4);     mma_bf16(kvacc[2 * g4 + 1], al[t], vh4 + 2);
                }
            }
            __syncthreads();
        }

        float* kvred = (float*)(sm + A_KVRED);
        #pragma unroll
        for (int g = 0; g < 8; g++) {
            int col = g * 8 + 2 * (lane & 3);
            int row = rb * 16 + (lane >> 2);
            float* dst = kvred + nh * 4096;
            dst[row * 64 + col]           = kvacc[g][0];
            dst[row * 64 + col + 1]       = kvacc[g][1];
            dst[(row + 8) * 64 + col]     = kvacc[g][2];
            dst[(row + 8) * 64 + col + 1] = kvacc[g][3];
        }
        __syncthreads();
        float* part = g_kv_part + (size_t)u * 4096;
        for (int idx = tid; idx < 4096; idx += 256)
            part[idx] = kvred[idx] + kvred[4096 + idx];

        __threadfence();
        __syncthreads();
        if (tid == 0) atomicAdd(&g_arrive[bh], 1u);
    }

    // ======================= B-unit claim loop =======================
    int last_bh = -1;
    for (;;) {
        __syncthreads();
        if (tid == 0) *(int*)(sm + S_CLAIM) = (int)atomicAdd(&g_ctrB, 1u);
        __syncthreads();
        const int u = *(volatile int*)(sm + S_CLAIM);
        if (u >= NU) break;
        const int bh = u >> 3, split = u & 7;

        if (bh != last_bh) {
            if (tid == 0) {
                while (*((volatile unsigned*)&g_arrive[bh]) < (unsigned)SPLITS) __nanosleep(64);
            }
            __syncthreads();
            __threadfence();
            const float* base = g_kv_part + (size_t)bh * SPLITS * 4096;
            __nv_bfloat16* kh = (__nv_bfloat16*)(sm + B_KVTH);
            __nv_bfloat16* kl = (__nv_bfloat16*)(sm + B_KVTL);
            for (int idx = tid; idx < 4096; idx += 256) {
                float s = 0.f;
                #pragma unroll
                for (int sp = 0; sp < SPLITS; sp++) s += base[sp * 4096 + idx];
                int e = idx >> 6, e2 = idx & 63;
                __nv_bfloat16 h, l;
                split2(s, h, l);
                kh[e2 * 72 + e] = h;
                kl[e2 * 72 + e] = l;
            }
            last_bh = bh;
            __syncthreads();
        }

        const int n0w = warp * 16;
        const float* bias_s = (const float*)(sm + S_BIAS);
        const float* qbase = q + (size_t)bh * 64 * NTOK + split * NSEG;
        float* obase = out + (size_t)bh * 64 * NTOK + split * NSEG;

        float4 qreg[8];
        ld_tile128(qbase, tid, qreg);

        for (int sc = 0; sc < CPS_B; sc++) {
            st_tile128(sm, B_QH, B_QL, qreg, tid);
            __syncthreads();

            float c3[8][4];
            #pragma unroll
            for (int g = 0; g < 8; g++)
                #pragma unroll
                for (int j = 0; j < 4; j++) c3[g][j] = 0.0f;

            #pragma unroll
            for (int kk = 0; kk < 4; kk++) {
                uint32_t aQh[4], aQl[4];
                ldsm4t(aQh, patB(sm32 + B_QH, LDQ, kk * 16, n0w, lane));
                ldsm4t(aQl, patB(sm32 + B_QL, LDQ, kk * 16, n0w, lane));
                #pragma unroll
                for (int g4 = 0; g4 < 4; g4++) {
                    uint32_t wbh[4], wbl[4];
                    ldsm4(wbh, patB(sm32 + S_WFH, LDA, g4 * 16, kk * 16, lane));
                    ldsm4(wbl, patB(sm32 + S_WFL, LDA, g4 * 16, kk * 16, lane));
                    mma_bf16(c3[2 * g4], aQh, wbh);     mma_bf16(c3[2 * g4 + 1], aQh, wbh + 2);
                    mma_bf16(c3[2 * g4], aQh, wbl);     mma_bf16(c3[2 * g4 + 1], aQh, wbl + 2);
                    mma_bf16(c3[2 * g4], aQl, wbh);     mma_bf16(c3[2 * g4 + 1], aQl, wbh + 2);
                }
            }
            __syncthreads();

            float oacc[8][4];
            #pragma unroll
            for (int g = 0; g < 8; g++)
                #pragma unroll
                for (int j = 0; j < 4; j++) oacc[g][j] = 0.0f;

            #pragma unroll
            for (int ks = 0; ks < 4; ks++) {
                const int g0 = 2 * ks, g1 = 2 * ks + 1;
                float b00 = bias_s[g0 * 8 + 2 * (lane & 3)], b01 = bias_s[g0 * 8 + 2 * (lane & 3) + 1];
                float b10 = bias_s[g1 * 8 + 2 * (lane & 3)], b11 = bias_s[g1 * 8 + 2 * (lane & 3) + 1];
                float v00 = fmaxf(c3[g0][0] + b00, 0.f), v01 = fmaxf(c3[g0][1] + b01, 0.f);
                float v02 = fmaxf(c3[g0][2] + b00, 0.f), v03 = fmaxf(c3[g0][3] + b01, 0.f);
                float v10 = fmaxf(c3[g1][0] + b10, 0.f), v11 = fmaxf(c3[g1][1] + b11, 0.f);
                float v12 = fmaxf(c3[g1][2] + b10, 0.f), v13 = fmaxf(c3[g1][3] + b11, 0.f);
                uint32_t a4h[4], a4l[4];
                split_pack(v00, v01, a4h[0], a4l[0]);
                split_pack(v02, v03, a4h[1], a4l[1]);
                split_pack(v10, v11, a4h[2], a4l[2]);
                split_pack(v12, v13, a4h[3], a4l[3]);

                #pragma unroll
                for (int g4 = 0; g4 < 4; g4++) {
                    uint32_t kbh[4], kbl[4];
                    ldsm4(kbh, patB(sm32 + B_KVTH, LDA, g4 * 16, ks * 16, lane));
                    ldsm4(kbl, patB(sm32 + B_KVTL, LDA, g4 * 16, ks * 16, lane));
                    mma_bf16(oacc[2 * g4], a4h, kbh);     mma_bf16(oacc[2 * g4 + 1], a4h, kbh + 2);
                    mma_bf16(oacc[2 * g4], a4h, kbl);     mma_bf16(oacc[2 * g4 + 1], a4h, kbl + 2);
                    mma_bf16(oacc[2 * g4], a4l, kbh);     mma_bf16(oacc[2 * g4 + 1], a4l, kbh + 2);
                }
            }

            if (sc + 1 < CPS_B) ld_tile128(qbase + (sc + 1) * 128, tid, qreg);

            // ---- direct STG of oacc: out[e2][n] ----
            {
                float* o = obase + sc * 128 + n0w + (lane >> 2);
                #pragma unroll
                for (int g4 = 0; g4 < 4; g4++) {
                    #pragma unroll
                    for (int p = 0; p < 2; p++) {
                        const int g = 2 * g4 + p;
                        const size_t e2c = (size_t)(g4 * 16 + p * 8 + (lane & 3) * 2);
                        o[e2c * NTOK]           = oacc[g][0];
                        o[(e2c + 1) * NTOK]     = oacc[g][1];
                        o[e2c * NTOK + 8]       = oacc[g][2];
                        o[(e2c + 1) * NTOK + 8] = oacc[g][3];
                    }
                }
            }
        }
    }
}

extern "C" void kernel_launch(void* const* d_in, const int* in_sizes, int n_in,
                              void* d_out, int out_size) {
    const float* q  = (const float*)d_in[0];
    const float* k  = (const float*)d_in[1];
    const float* v  = (const float*)d_in[2];
    const float* Wf = (const float*)d_in[3];
    const float* bf = (const float*)d_in[4];
    float* out = (float*)d_out;

    cudaFuncSetAttribute(fused, cudaFuncAttributeMaxDynamicSharedMemorySize, SMEM_TOTAL);
    resetk<<<1, 64>>>();
    fused<<<GRID, 256, SMEM_TOTAL>>>(q, k, v, Wf, bf, out);
}

// round 14
// speedup vs baseline: 1.0252x; 1.0252x over previous
#include <cuda_runtime.h>
#include <cuda_bf16.h>
#include <cstdint>

constexpr int NTOK = 4096;
constexpr int BH = 64, SPLITS = 8, NSEG = 512;
constexpr int CPS_A = NSEG / 64;     // 8 chunks of 64 tokens
constexpr int CPS_B = NSEG / 128;    // 4 chunks of 128 tokens
constexpr int NU = BH * SPLITS;      // 512 units per phase
constexpr int GRID = 296;

__device__ float    g_kv_part[(size_t)BH * SPLITS * 64 * 64];
__device__ unsigned g_arrive[BH];
__device__ unsigned g_ctrA, g_ctrB;

// ---- smem byte offsets ----
constexpr int LDA = 144;                              // 72-bf16 rows
constexpr int A_KH = 0, A_KL = 9216, A_VH = 18432, A_VL = 27648;
constexpr int S_WFH = 36864, S_WFL = 46080, S_BIAS = 55296;
constexpr int A_KVRED = 55552;                        // 2 x 16 KB
constexpr int LDQ = 272;
constexpr int B_QH = 0, B_QL = 17408;
constexpr int B_KVTH = 55552, B_KVTL = 64768;
constexpr int S_CLAIM = 88320;
constexpr int SMEM_TOTAL = 88448;

// ---------------- PTX helpers ----------------
__device__ __forceinline__ void ldsm4(uint32_t r[4], uint32_t a) {
    asm volatile("ldmatrix.sync.aligned.m8n8.x4.shared.b16 {%0,%1,%2,%3},[%4];"
                 : "=r"(r[0]), "=r"(r[1]), "=r"(r[2]), "=r"(r[3]) : "r"(a));
}
__device__ __forceinline__ void ldsm4t(uint32_t r[4], uint32_t a) {
    asm volatile("ldmatrix.sync.aligned.m8n8.x4.trans.shared.b16 {%0,%1,%2,%3},[%4];"
                 : "=r"(r[0]), "=r"(r[1]), "=r"(r[2]), "=r"(r[3]) : "r"(a));
}
// non-volatile: pure register op, compiler may schedule freely
__device__ __forceinline__ void mma_bf16(float c[4], const uint32_t a[4], const uint32_t b[2]) {
    asm("mma.sync.aligned.m16n8k16.row.col.f32.bf16.bf16.f32 "
        "{%0,%1,%2,%3},{%4,%5,%6,%7},{%8,%9},{%0,%1,%2,%3};"
        : "+f"(c[0]), "+f"(c[1]), "+f"(c[2]), "+f"(c[3])
        : "r"(a[0]), "r"(a[1]), "r"(a[2]), "r"(a[3]), "r"(b[0]), "r"(b[1]));
}
__device__ __forceinline__ uint32_t patA(uint32_t base, int ldB, int r0, int c0, int lane) {
    return base + (uint32_t)((r0 + (lane & 15)) * ldB + (c0 + ((lane >> 4) << 3)) * 2);
}
__device__ __forceinline__ uint32_t patB(uint32_t base, int ldB, int r0, int c0, int lane) {
    return base + (uint32_t)((r0 + (lane & 7) + ((lane >> 4) << 3)) * ldB
                             + (c0 + (((lane >> 3) & 1) << 3)) * 2);
}
__device__ __forceinline__ void split2(float x, __nv_bfloat16& hi, __nv_bfloat16& lo) {
    hi = __float2bfloat16(x);
    lo = __float2bfloat16(x - __bfloat162float(hi));
}
__device__ __forceinline__ void split_pack(float x0, float x1, uint32_t& hi, uint32_t& lo) {
    __nv_bfloat16 h0 = __float2bfloat16(x0), h1 = __float2bfloat16(x1);
    float r0 = x0 - __bfloat162float(h0), r1 = x1 - __bfloat162float(h1);
    __nv_bfloat162 hp = __halves2bfloat162(h0, h1);
    __nv_bfloat162 lp = __halves2bfloat162(__float2bfloat16(r0), __float2bfloat16(r1));
    hi = *(uint32_t*)&hp; lo = *(uint32_t*)&lp;
}
__device__ __forceinline__ void split_store4w(float4 x, __nv_bfloat16* hi, __nv_bfloat16* lo) {
    uint32_t h0, l0, h1, l1;
    split_pack(x.x, x.y, h0, l0);
    split_pack(x.z, x.w, h1, l1);
    *(uint2*)hi = make_uint2(h0, h1);
    *(uint2*)lo = make_uint2(l0, l1);
}
__device__ __forceinline__ void ld_tile64(const float* __restrict__ g, int tid, float4 r[4]) {
    #pragma unroll
    for (int i = 0; i < 4; i++) {
        int idx4 = tid + i * 256;
        r[i] = *(const float4*)(g + (size_t)(idx4 >> 4) * NTOK + (idx4 & 15) * 4);
    }
}
__device__ __forceinline__ void st_tile64(char* sm, int offH, int offL, const float4 r[4], int tid) {
    #pragma unroll
    for (int i = 0; i < 4; i++) {
        int idx4 = tid + i * 256;
        int row = idx4 >> 4, c = (idx4 & 15) * 4;
        split_store4w(r[i], (__nv_bfloat16*)(sm + offH) + row * 72 + c,
                            (__nv_bfloat16*)(sm + offL) + row * 72 + c);
    }
}
__device__ __forceinline__ void ld_tile128(const float* __restrict__ g, int tid, float4 r[8]) {
    #pragma unroll
    for (int i = 0; i < 8; i++) {
        int idx4 = tid + i * 256;
        r[i] = *(const float4*)(g + (size_t)(idx4 >> 5) * NTOK + (idx4 & 31) * 4);
    }
}
__device__ __forceinline__ void st_tile128(char* sm, int offH, int offL, const float4 r[8], int tid) {
    #pragma unroll
    for (int i = 0; i < 8; i++) {
        int idx4 = tid + i * 256;
        int row = idx4 >> 5, c = (idx4 & 31) * 4;
        split_store4w(r[i], (__nv_bfloat16*)(sm + offH) + row * 136 + c,
                            (__nv_bfloat16*)(sm + offL) + row * 136 + c);
    }
}

__global__ void resetk() {
    if (threadIdx.x == 0) { g_ctrA = 0; g_ctrB = 0; }
    if (threadIdx.x < BH) g_arrive[threadIdx.x] = 0;
}

__global__ void __launch_bounds__(256, 2) fused(const float* __restrict__ q,
                                                const float* __restrict__ k,
                                                const float* __restrict__ v,
                                                const float* __restrict__ Wf,
                                                const float* __restrict__ bf,
                                                float* __restrict__ out) {
    extern __shared__ __align__(16) char sm[];
    const uint32_t sm32 = (uint32_t)__cvta_generic_to_shared(sm);
    const int tid = threadIdx.x, lane = tid & 31, warp = tid >> 5;

    // Wf split (persists across all units)
    #pragma unroll
    for (int i = 0; i < 16; i++) {
        int idx = tid + i * 256;
        int r = idx >> 6, c = idx & 63;
        __nv_bfloat16 h, l;
        split2(Wf[idx], h, l);
        ((__nv_bfloat16*)(sm + S_WFH))[r * 72 + c] = h;
        ((__nv_bfloat16*)(sm + S_WFL))[r * 72 + c] = l;
    }
    if (tid < 64) ((float*)(sm + S_BIAS))[tid] = bf[tid];

    const int rb = warp >> 1, nh = warp & 1;

    // ======================= A-unit claim loop =======================
    for (;;) {
        __syncthreads();
        if (tid == 0) *(int*)(sm + S_CLAIM) = (int)atomicAdd(&g_ctrA, 1u);
        __syncthreads();
        const int u = *(volatile int*)(sm + S_CLAIM);
        if (u >= NU) break;
        const int bh = u >> 3, split = u & 7;

        const float bias_r0 = ((float*)(sm + S_BIAS))[rb * 16 + (lane >> 2)];
        const float bias_r1 = ((float*)(sm + S_BIAS))[rb * 16 + (lane >> 2) + 8];

        float kvacc[8][4];
        #pragma unroll
        for (int g = 0; g < 8; g++)
            #pragma unroll
            for (int j = 0; j < 4; j++) kvacc[g][j] = 0.0f;

        const float* kbase = k + (size_t)bh * 64 * NTOK + split * NSEG;
        const float* vbase = v + (size_t)bh * 64 * NTOK + split * NSEG;

        float4 kreg[4], vreg[4];
        ld_tile64(kbase, tid, kreg);
        ld_tile64(vbase, tid, vreg);

        for (int sc = 0; sc < CPS_A; sc++) {
            st_tile64(sm, A_KH, A_KL, kreg, tid);
            st_tile64(sm, A_VH, A_VL, vreg, tid);
            __syncthreads();
            if (sc + 1 < CPS_A) {
                ld_tile64(kbase + (sc + 1) * 64, tid, kreg);
                ld_tile64(vbase + (sc + 1) * 64, tid, vreg);
            }

            float c[2][2][4];
            #pragma unroll
            for (int t = 0; t < 2; t++)
                #pragma unroll
                for (int g = 0; g < 2; g++)
                    #pragma unroll
                    for (int j = 0; j < 4; j++) c[t][g][j] = 0.0f;

            #pragma unroll
            for (int kk = 0; kk < 4; kk++) {
                uint32_t wh4[4], wl4[4];
                ldsm4(wh4, patA(sm32 + S_WFH, LDA, rb * 16, kk * 16, lane));
                ldsm4(wl4, patA(sm32 + S_WFL, LDA, rb * 16, kk * 16, lane));
                #pragma unroll
                for (int t = 0; t < 2; t++) {
                    const int n0 = nh * 32 + t * 16;
                    uint32_t bh4[4], bl4[4];
                    ldsm4t(bh4, patA(sm32 + A_KH, LDA, kk * 16, n0, lane));
                    ldsm4t(bl4, patA(sm32 + A_KL, LDA, kk * 16, n0, lane));
                    mma_bf16(c[t][0], wh4, bh4);     mma_bf16(c[t][1], wh4, bh4 + 2);
                    mma_bf16(c[t][0], wh4, bl4);     mma_bf16(c[t][1], wh4, bl4 + 2);
                    mma_bf16(c[t][0], wl4, bh4);     mma_bf16(c[t][1], wl4, bh4 + 2);
                }
            }

            uint32_t ah[2][4], al[2][4];
            #pragma unroll
            for (int t = 0; t < 2; t++) {
                float v00 = fmaxf(c[t][0][0] + bias_r0, 0.f), v01 = fmaxf(c[t][0][1] + bias_r0, 0.f);
                float v02 = fmaxf(c[t][0][2] + bias_r1, 0.f), v03 = fmaxf(c[t][0][3] + bias_r1, 0.f);
                float v10 = fmaxf(c[t][1][0] + bias_r0, 0.f), v11 = fmaxf(c[t][1][1] + bias_r0, 0.f);
                float v12 = fmaxf(c[t][1][2] + bias_r1, 0.f), v13 = fmaxf(c[t][1][3] + bias_r1, 0.f);
                split_pack(v00, v01, ah[t][0], al[t][0]);
                split_pack(v02, v03, ah[t][1], al[t][1]);
                split_pack(v10, v11, ah[t][2], al[t][2]);
                split_pack(v12, v13, ah[t][3], al[t][3]);
            }

            #pragma unroll
            for (int g4 = 0; g4 < 4; g4++) {
                #pragma unroll
                for (int t = 0; t < 2; t++) {
                    const int n0 = nh * 32 + t * 16;
                    uint32_t vh4[4], vl4[4];
                    ldsm4(vh4, patB(sm32 + A_VH, LDA, g4 * 16, n0, lane));
                    ldsm4(vl4, patB(sm32 + A_VL, LDA, g4 * 16, n0, lane));
                    mma_bf16(kvacc[2 * g4], ah[t], vh4);     mma_bf16(kvacc[2 * g4 + 1], ah[t], vh4 + 2);
                    mma_bf16(kvacc[2 * g4], ah[t], vl4);     mma_bf16(kvacc[2 * g4 + 1], ah[t], vl4 + 2);
                    mma_bf16(kvacc[2 * g4], al[t], vh4);     mma_bf16(kvacc[2 * g4 + 1], al[t], vh4 + 2);
                }
            }
            __syncthreads();
        }

        float* kvred = (float*)(sm + A_KVRED);
        #pragma unroll
        for (int g = 0; g < 8; g++) {
            int col = g * 8 + 2 * (lane & 3);
            int row = rb * 16 + (lane >> 2);
            float* dst = kvred + nh * 4096;
            dst[row * 64 + col]           = kvacc[g][0];
            dst[row * 64 + col + 1]       = kvacc[g][1];
            dst[(row + 8) * 64 + col]     = kvacc[g][2];
            dst[(row + 8) * 64 + col + 1] = kvacc[g][3];
        }
        __syncthreads();
        float* part = g_kv_part + (size_t)u * 4096;
        for (int idx = tid; idx < 4096; idx += 256)
            part[idx] = kvred[idx] + kvred[4096 + idx];

        __threadfence();
        __syncthreads();
        if (tid == 0) atomicAdd(&g_arrive[bh], 1u);
    }

    // ======================= B-unit claim loop =======================
    int last_bh = -1;
    for (;;) {
        __syncthreads();
        if (tid == 0) *(int*)(sm + S_CLAIM) = (int)atomicAdd(&g_ctrB, 1u);
        __syncthreads();
        const int u = *(volatile int*)(sm + S_CLAIM);
        if (u >= NU) break;
        const int bh = u >> 3, split = u & 7;

        const float* qbase = q + (size_t)bh * 64 * NTOK + split * NSEG;
        float* obase = out + (size_t)bh * 64 * NTOK + split * NSEG;

        // issue first Q-tile loads BEFORE the spin/reduce: LDG latency overlaps the wait
        float4 qreg[8];
        ld_tile128(qbase, tid, qreg);

        if (bh != last_bh) {
            if (tid == 0) {
                while (*((volatile unsigned*)&g_arrive[bh]) < (unsigned)SPLITS) __nanosleep(64);
            }
            __syncthreads();
            __threadfence();
            const float* base = g_kv_part + (size_t)bh * SPLITS * 4096;
            __nv_bfloat16* kh = (__nv_bfloat16*)(sm + B_KVTH);
            __nv_bfloat16* kl = (__nv_bfloat16*)(sm + B_KVTL);
            for (int idx = tid; idx < 4096; idx += 256) {
                float s = 0.f;
                #pragma unroll
                for (int sp = 0; sp < SPLITS; sp++) s += base[sp * 4096 + idx];
                int e = idx >> 6, e2 = idx & 63;
                __nv_bfloat16 h, l;
                split2(s, h, l);
                kh[e2 * 72 + e] = h;
                kl[e2 * 72 + e] = l;
            }
            last_bh = bh;
            __syncthreads();
        }

        const int n0w = warp * 16;
        const float* bias_s = (const float*)(sm + S_BIAS);

        for (int sc = 0; sc < CPS_B; sc++) {
            st_tile128(sm, B_QH, B_QL, qreg, tid);
            __syncthreads();
            // prefetch next chunk IMMEDIATELY: overlaps all MMA work below
            if (sc + 1 < CPS_B) ld_tile128(qbase + (sc + 1) * 128, tid, qreg);

            float c3[8][4];
            #pragma unroll
            for (int g = 0; g < 8; g++)
                #pragma unroll
                for (int j = 0; j < 4; j++) c3[g][j] = 0.0f;

            #pragma unroll
            for (int kk = 0; kk < 4; kk++) {
                uint32_t aQh[4], aQl[4];
                ldsm4t(aQh, patB(sm32 + B_QH, LDQ, kk * 16, n0w, lane));
                ldsm4t(aQl, patB(sm32 + B_QL, LDQ, kk * 16, n0w, lane));
                #pragma unroll
                for (int g4 = 0; g4 < 4; g4++) {
                    uint32_t wbh[4], wbl[4];
                    ldsm4(wbh, patB(sm32 + S_WFH, LDA, g4 * 16, kk * 16, lane));
                    ldsm4(wbl, patB(sm32 + S_WFL, LDA, g4 * 16, kk * 16, lane));
                    mma_bf16(c3[2 * g4], aQh, wbh);     mma_bf16(c3[2 * g4 + 1], aQh, wbh + 2);
                    mma_bf16(c3[2 * g4], aQh, wbl);     mma_bf16(c3[2 * g4 + 1], aQh, wbl + 2);
                    mma_bf16(c3[2 * g4], aQl, wbh);     mma_bf16(c3[2 * g4 + 1], aQl, wbh + 2);
                }
            }
            __syncthreads();   // Q reads done -> next st_tile128 safe

            float oacc[8][4];
            #pragma unroll
            for (int g = 0; g < 8; g++)
                #pragma unroll
                for (int j = 0; j < 4; j++) oacc[g][j] = 0.0f;

            #pragma unroll
            for (int ks = 0; ks < 4; ks++) {
                const int g0 = 2 * ks, g1 = 2 * ks + 1;
                float b00 = bias_s[g0 * 8 + 2 * (lane & 3)], b01 = bias_s[g0 * 8 + 2 * (lane & 3) + 1];
                float b10 = bias_s[g1 * 8 + 2 * (lane & 3)], b11 = bias_s[g1 * 8 + 2 * (lane & 3) + 1];
                float v00 = fmaxf(c3[g0][0] + b00, 0.f), v01 = fmaxf(c3[g0][1] + b01, 0.f);
                float v02 = fmaxf(c3[g0][2] + b00, 0.f), v03 = fmaxf(c3[g0][3] + b01, 0.f);
                float v10 = fmaxf(c3[g1][0] + b10, 0.f), v11 = fmaxf(c3[g1][1] + b11, 0.f);
                float v12 = fmaxf(c3[g1][2] + b10, 0.f), v13 = fmaxf(c3[g1][3] + b11, 0.f);
                uint32_t a4h[4], a4l[4];
                split_pack(v00, v01, a4h[0], a4l[0]);
                split_pack(v02, v03, a4h[1], a4l[1]);
                split_pack(v10, v11, a4h[2], a4l[2]);
                split_pack(v12, v13, a4h[3], a4l[3]);

                #pragma unroll
                for (int g4 = 0; g4 < 4; g4++) {
                    uint32_t kbh[4], kbl[4];
                    ldsm4(kbh, patB(sm32 + B_KVTH, LDA, g4 * 16, ks * 16, lane));
                    ldsm4(kbl, patB(sm32 + B_KVTL, LDA, g4 * 16, ks * 16, lane));
                    mma_bf16(oacc[2 * g4], a4h, kbh);     mma_bf16(oacc[2 * g4 + 1], a4h, kbh + 2);
                    mma_bf16(oacc[2 * g4], a4h, kbl);     mma_bf16(oacc[2 * g4 + 1], a4h, kbl + 2);
                    mma_bf16(oacc[2 * g4], a4l, kbh);     mma_bf16(oacc[2 * g4 + 1], a4l, kbh + 2);
                }
            }

            // ---- direct STG of oacc: out[e2][n] ----
            {
                float* o = obase + sc * 128 + n0w + (lane >> 2);
                #pragma unroll
                for (int g4 = 0; g4 < 4; g4++) {
                    #pragma unroll
                    for (int p = 0; p < 2; p++) {
                        const int g = 2 * g4 + p;
                        const size_t e2c = (size_t)(g4 * 16 + p * 8 + (lane & 3) * 2);
                        o[e2c * NTOK]           = oacc[g][0];
                        o[(e2c + 1) * NTOK]     = oacc[g][1];
                        o[e2c * NTOK + 8]       = oacc[g][2];
                        o[(e2c + 1) * NTOK + 8] = oacc[g][3];
                    }
                }
            }
        }
    }
}

extern "C" void kernel_launch(void* const* d_in, const int* in_sizes, int n_in,
                              void* d_out, int out_size) {
    const float* q  = (const float*)d_in[0];
    const float* k  = (const float*)d_in[1];
    const float* v  = (const float*)d_in[2];
    const float* Wf = (const float*)d_in[3];
    const float* bf = (const float*)d_in[4];
    float* out = (float*)d_out;

    cudaFuncSetAttribute(fused, cudaFuncAttributeMaxDynamicSharedMemorySize, SMEM_TOTAL);
    resetk<<<1, 64>>>();
    fused<<<GRID, 256, SMEM_TOTAL>>>(q, k, v, Wf, bf, out);
}